// round 14
// baseline (speedup 1.0000x reference)
#include <cuda_runtime.h>
#include <cuda_bf16.h>
#include <cstdint>

// ============================================================================
// PhaseMoE via mma.sync (HMMA m16n8k16 bf16), hi/lo 3-MMA split.
// R13 = R12 + (a) MMA burst reordered ks{term{mt{nt}}} so RAW-dependent HMMAs
// on the same accumulator are 8 issue slots apart (latency hidden; per-
// accumulator order unchanged -> bit-identical), (b) init_out fused into the
// e==0 L3 epilogue (store c + sum_k p_k*b3_k instead of RMW; one less kernel
// and one less full read of out).
// 512 threads, 4x4 warp grid, 32x32 warp tile.
// ============================================================================

#define B_TOK 32768
#define KEXP  8
#define EIN   1280
#define HID   128
#define LAT   256

#define ROWB   80
#define TILEB  (128 * ROWB)     // 10240 B per 128x32 tile
#define TILEE  (128 * 40)       // 5120 bf16 elems per padded tile

// smem map: 3 stage buffers x 4 tiles, 4 h-chunks x hi/lo, aux, b3
#define STG(s, t) ((uint32_t)(((s) * 4 + (t)) * TILEB))   // t:0 Ahi 1 Alo 2 Bhi 3 Blo
#define HOF(c, h) ((uint32_t)((12 + (c) * 2 + (h)) * TILEB))
#define AUX       ((uint32_t)(20 * TILEB))
#define B3OFF     (AUX + 4096)
#define SMEM_TOTAL (20 * TILEB + 4096 + 8192)

// ---- pre-tiled bf16 hi/lo scratch (__device__ globals) ----
__device__ __align__(16) __nv_bfloat16 g_xhi[(size_t)256 * 40 * TILEE];
__device__ __align__(16) __nv_bfloat16 g_xlo[(size_t)256 * 40 * TILEE];
__device__ __align__(16) __nv_bfloat16 g_w1hi[KEXP * 40 * TILEE];
__device__ __align__(16) __nv_bfloat16 g_w1lo[KEXP * 40 * TILEE];
__device__ __align__(16) __nv_bfloat16 g_w2hi[KEXP * 4 * TILEE];
__device__ __align__(16) __nv_bfloat16 g_w2lo[KEXP * 4 * TILEE];
__device__ __align__(16) __nv_bfloat16 g_w3hi[KEXP * 2 * 4 * TILEE];
__device__ __align__(16) __nv_bfloat16 g_w3lo[KEXP * 2 * 4 * TILEE];

// ============================ helpers =======================================
__device__ __forceinline__ uint32_t smem_u32(const void* p) {
    uint32_t a;
    asm("{ .reg .u64 t; cvta.to.shared.u64 t, %1; cvt.u32.u64 %0, t; }"
        : "=r"(a) : "l"(p));
    return a;
}
#define MBAR_INIT(mb, c) asm volatile("mbarrier.init.shared.b64 [%0], %1;" :: "r"(mb), "r"(c) : "memory")
#define MBAR_EXPECT_TX(mb, tx) asm volatile("mbarrier.arrive.expect_tx.shared.b64 _, [%0], %1;" :: "r"(mb), "r"(tx) : "memory")
#define MBAR_ARRIVE(mb) asm volatile("mbarrier.arrive.shared.b64 _, [%0];" :: "r"(mb) : "memory")

__device__ __forceinline__ void bulk_g2s(uint32_t dst, const void* src,
                                         uint32_t bytes, uint32_t mb) {
    asm volatile(
        "cp.async.bulk.shared::cta.global.mbarrier::complete_tx::bytes "
        "[%0], [%1], %2, [%3];"
        :: "r"(dst), "l"(src), "r"(bytes), "r"(mb) : "memory");
}

__device__ __forceinline__ void mbar_wait(uint32_t mb, uint32_t parity) {
    asm volatile(
        "{\n\t.reg .pred P1;\n\t"
        "WAIT_%=:\n\t"
        "mbarrier.try_wait.parity.acquire.cta.shared::cta.b64 P1, [%0], %1, 0x989680;\n\t"
        "@P1 bra.uni DONE_%=;\n\t"
        "bra.uni WAIT_%=;\n\t"
        "DONE_%=:\n\t}"
        :: "r"(mb), "r"(parity) : "memory");
}

__device__ __forceinline__ void ldsm4(uint32_t addr, uint32_t* r) {
    asm volatile("ldmatrix.sync.aligned.m8n8.x4.shared.b16 {%0,%1,%2,%3}, [%4];"
                 : "=r"(r[0]), "=r"(r[1]), "=r"(r[2]), "=r"(r[3]) : "r"(addr));
}

__device__ __forceinline__ void mma16816(float* c, const uint32_t* a,
                                         uint32_t b0, uint32_t b1) {
    asm volatile(
        "mma.sync.aligned.m16n8k16.row.col.f32.bf16.bf16.f32 "
        "{%0,%1,%2,%3}, {%4,%5,%6,%7}, {%8,%9}, {%0,%1,%2,%3};"
        : "+f"(c[0]), "+f"(c[1]), "+f"(c[2]), "+f"(c[3])
        : "r"(a[0]), "r"(a[1]), "r"(a[2]), "r"(a[3]), "r"(b0), "r"(b1));
}

// MMA burst: ks{term{mt{nt}}}. Per-accumulator op order is IDENTICAL to the
// old ks{mt{nt{t0,t1,t2}}} (bit-identical results), but dependent HMMAs are
// now 8 issue slots apart instead of adjacent -> RAW latency hidden.
__device__ __forceinline__ void mma_burst(float c[2][4][4],
        uint32_t ah[2][2][4], uint32_t al[2][2][4],
        uint32_t bh[2][2][4], uint32_t bl[2][2][4]) {
#pragma unroll
    for (int ks = 0; ks < 2; ++ks)
#pragma unroll
        for (int t = 0; t < 3; ++t)
#pragma unroll
            for (int mt = 0; mt < 2; ++mt)
#pragma unroll
                for (int nt = 0; nt < 4; ++nt) {
                    int pr = nt >> 1, hf = (nt & 1) * 2;
                    if (t == 0)
                        mma16816(c[mt][nt], ah[ks][mt], bh[ks][pr][hf], bh[ks][pr][hf + 1]);
                    else if (t == 1)
                        mma16816(c[mt][nt], ah[ks][mt], bl[ks][pr][hf], bl[ks][pr][hf + 1]);
                    else
                        mma16816(c[mt][nt], al[ks][mt], bh[ks][pr][hf], bh[ks][pr][hf + 1]);
                }
}

// L1 consume: A and B both live in the stage ring.
__device__ __forceinline__ void consume_l1(float c[2][4][4], uint32_t sb,
        int s, uint32_t fb, uint32_t parity,
        int wm, int wn, uint32_t aoff, uint32_t boff, int lane) {
    mbar_wait(fb, parity);
    uint32_t ah[2][2][4], al[2][2][4], bh[2][2][4], bl[2][2][4];
#pragma unroll
    for (int ks = 0; ks < 2; ++ks) {
#pragma unroll
        for (int mt = 0; mt < 2; ++mt) {
            uint32_t base = (uint32_t)((wm * 32 + mt * 16) * ROWB + ks * 32) + aoff;
            ldsm4(sb + STG(s, 0) + base, ah[ks][mt]);
            ldsm4(sb + STG(s, 1) + base, al[ks][mt]);
        }
#pragma unroll
        for (int pr = 0; pr < 2; ++pr) {
            uint32_t base = (uint32_t)((wn * 32 + pr * 16) * ROWB + ks * 32) + boff;
            ldsm4(sb + STG(s, 2) + base, bh[ks][pr]);
            ldsm4(sb + STG(s, 3) + base, bl[ks][pr]);
        }
    }
    __syncwarp();
    if (lane == 0) MBAR_ARRIVE(fb + 8);   // smem free; MMAs read registers
    mma_burst(c, ah, al, bh, bl);
}

// L2/L3 consume: A in HOF (stable), B in the stage ring.
__device__ __forceinline__ void consume_h(float c[2][4][4], uint32_t sb,
        uint32_t Ahi, uint32_t Alo, int s, uint32_t fb, uint32_t parity,
        int wm, int wn, uint32_t aoff, uint32_t boff, int lane) {
    uint32_t ah[2][2][4], al[2][2][4], bh[2][2][4], bl[2][2][4];
#pragma unroll
    for (int ks = 0; ks < 2; ++ks)
#pragma unroll
        for (int mt = 0; mt < 2; ++mt) {
            uint32_t base = (uint32_t)((wm * 32 + mt * 16) * ROWB + ks * 32) + aoff;
            ldsm4(sb + Ahi + base, ah[ks][mt]);
            ldsm4(sb + Alo + base, al[ks][mt]);
        }
    mbar_wait(fb, parity);
#pragma unroll
    for (int ks = 0; ks < 2; ++ks)
#pragma unroll
        for (int pr = 0; pr < 2; ++pr) {
            uint32_t base = (uint32_t)((wn * 32 + pr * 16) * ROWB + ks * 32) + boff;
            ldsm4(sb + STG(s, 2) + base, bh[ks][pr]);
            ldsm4(sb + STG(s, 3) + base, bl[ks][pr]);
        }
    __syncwarp();
    if (lane == 0) MBAR_ARRIVE(fb + 8);
    mma_burst(c, ah, al, bh, bl);
}

__device__ __forceinline__ void split_pack(float h0, float h1,
                                           uint32_t& hip, uint32_t& lop) {
    __nv_bfloat16 h0h = __float2bfloat16(h0);
    __nv_bfloat16 h1h = __float2bfloat16(h1);
    hip = (uint32_t)__bfloat16_as_ushort(h0h) |
          ((uint32_t)__bfloat16_as_ushort(h1h) << 16);
    lop = (uint32_t)__bfloat16_as_ushort(__float2bfloat16(h0 - __bfloat162float(h0h))) |
          ((uint32_t)__bfloat16_as_ushort(__float2bfloat16(h1 - __bfloat162float(h1h))) << 16);
}

#define ZERO_C() do { \
    _Pragma("unroll") for (int mt = 0; mt < 2; ++mt) \
    _Pragma("unroll") for (int nt = 0; nt < 4; ++nt) \
    _Pragma("unroll") for (int q = 0; q < 4; ++q) c[mt][nt][q] = 0.f; } while (0)

// ======================= prep kernels (tiled layout) ========================
__global__ void convert_x_kernel(const float* __restrict__ u,
                                 const float* __restrict__ cond) {
    const int total = B_TOK * EIN;
    for (int i = blockIdx.x * blockDim.x + threadIdx.x; i < total;
         i += gridDim.x * blockDim.x) {
        int b = i / EIN, k = i - b * EIN;
        float v = (k < 256) ? u[(size_t)b * 256 + k]
                            : cond[(size_t)b * 1024 + (k - 256)];
        int t = b >> 7, m = b & 127, c = k >> 5, kk = k & 31;
        size_t dst = ((size_t)(t * 40 + c) * 128 + m) * 40 + kk;
        __nv_bfloat16 hi = __float2bfloat16(v);
        g_xhi[dst] = hi;
        g_xlo[dst] = __float2bfloat16(v - __bfloat162float(hi));
    }
}

__global__ void convert_w_kernel(const float* __restrict__ W1,
                                 const float* __restrict__ W2,
                                 const float* __restrict__ W3) {
    const int N1 = KEXP * HID * EIN;
    const int N2 = KEXP * HID * HID;
    const int N3 = KEXP * LAT * HID;
    const int total = N1 + N2 + N3;
    for (int i = blockIdx.x * blockDim.x + threadIdx.x; i < total;
         i += gridDim.x * blockDim.x) {
        float v;
        size_t dst;
        __nv_bfloat16 *dh, *dl;
        if (i < N1) {
            int e = i / (HID * EIN), r = i - e * (HID * EIN);
            int n = r / EIN, k = r - n * EIN;
            int c = k >> 5, kk = k & 31;
            v = W1[((size_t)e * 1281 + k) * HID + n];
            dst = ((size_t)(e * 40 + c) * 128 + n) * 40 + kk;
            dh = g_w1hi; dl = g_w1lo;
        } else if (i < N1 + N2) {
            int j = i - N1;
            int e = j / (HID * HID), r = j - e * (HID * HID);
            int n = r / HID, k = r - n * HID;
            int c = k >> 5, kk = k & 31;
            v = W2[((size_t)e * HID + k) * HID + n];
            dst = ((size_t)(e * 4 + c) * 128 + n) * 40 + kk;
            dh = g_w2hi; dl = g_w2lo;
        } else {
            int j = i - N1 - N2;
            int e = j / (LAT * HID), r = j - e * (LAT * HID);
            int n = r / HID, k = r - n * HID;
            int nh = n >> 7, nn = n & 127, c = k >> 5, kk = k & 31;
            v = W3[((size_t)e * HID + k) * LAT + n];
            dst = ((size_t)((e * 2 + nh) * 4 + c) * 128 + nn) * 40 + kk;
            dh = g_w3hi; dl = g_w3lo;
        }
        __nv_bfloat16 hi = __float2bfloat16(v);
        dh[dst] = hi;
        dl[dst] = __float2bfloat16(v - __bfloat162float(hi));
    }
}

// =========================== main kernel ====================================
#define FILL4(xh_, xl_, wh_, wl_) do { \
    int s_ = pg % 3; uint32_t par_ = (uint32_t)(((pg / 3) + 1) & 1); \
    uint32_t fb_ = mb0 + s_ * 16, eb_ = fb_ + 8; \
    mbar_wait(eb_, par_); \
    MBAR_EXPECT_TX(fb_, 4 * TILEB); \
    bulk_g2s(sb + STG(s_, 0), (xh_), TILEB, fb_); \
    bulk_g2s(sb + STG(s_, 1), (xl_), TILEB, fb_); \
    bulk_g2s(sb + STG(s_, 2), (wh_), TILEB, fb_); \
    bulk_g2s(sb + STG(s_, 3), (wl_), TILEB, fb_); \
    ++pg; } while (0)

#define FILL2(wh_, wl_) do { \
    int s_ = pg % 3; uint32_t par_ = (uint32_t)(((pg / 3) + 1) & 1); \
    uint32_t fb_ = mb0 + s_ * 16, eb_ = fb_ + 8; \
    mbar_wait(eb_, par_); \
    MBAR_EXPECT_TX(fb_, 2 * TILEB); \
    bulk_g2s(sb + STG(s_, 2), (wh_), TILEB, fb_); \
    bulk_g2s(sb + STG(s_, 3), (wl_), TILEB, fb_); \
    ++pg; } while (0)

__global__ __launch_bounds__(512, 1)
void phase_moe_mma(const float* __restrict__ tau,
                   const float* __restrict__ p_hat,
                   const float* __restrict__ W1,
                   const float* __restrict__ b1,
                   const float* __restrict__ b2,
                   const float* __restrict__ b3,
                   float* __restrict__ out) {
    extern __shared__ __align__(128) char smem[];
    const uint32_t sb = smem_u32(smem);
    const int tid  = threadIdx.x;
    const int lane = tid & 31;
    const int w    = tid >> 5;
    const int wm   = w >> 2, wn = w & 3;
    const int lr   = lane >> 2, lc = lane & 3;
    const int b0   = blockIdx.x * 128;
    const int btile = blockIdx.x;

    const uint32_t aoff = (uint32_t)(((lane & 7) + ((lane >> 3) & 1) * 8) * ROWB
                                     + ((lane >> 4) & 1) * 16);
    const uint32_t boff = (uint32_t)(((lane & 7) + ((lane >> 4) & 1) * 8) * ROWB
                                     + ((lane >> 3) & 1) * 16);

    float* b1s  = reinterpret_cast<float*>(smem + AUX);          // 128
    float* b2s  = reinterpret_cast<float*>(smem + AUX + 512);    // 128
    float* w1l  = reinterpret_cast<float*>(smem + AUX + 1024);   // 128
    float* taus = reinterpret_cast<float*>(smem + AUX + 1536);   // 128
    float* b3s  = reinterpret_cast<float*>(smem + B3OFF);        // 8*256
    const uint32_t mb0 = sb + AUX + 2048;                        // 3x(full,empty)

    if (tid == 0) {
#pragma unroll
        for (int s = 0; s < 3; ++s) {
            MBAR_INIT(mb0 + s * 16,     1);    // full: expect_tx arrival
            MBAR_INIT(mb0 + s * 16 + 8, 16);   // empty: one arrive per warp
        }
    }
    if (tid < 128) taus[tid] = tau[b0 + tid];
    for (int i = tid; i < KEXP * LAT; i += 512) b3s[i] = b3[i];
    __syncthreads();   // mbarrier init + b3s visible

    int pg = 0;   // producer fill counter (tid0)
    int cg = 0;   // consumer counter (all threads)
    float c[2][4][4];

    for (int e = 0; e < KEXP; ++e) {
        __syncthreads();   // bias smem reuse safe; h tiles free
        if (tid < 128) {
            b1s[tid] = b1[e * HID + tid];
            b2s[tid] = b2[e * HID + tid];
            w1l[tid] = W1[((size_t)e * 1281 + 1280) * HID + tid];
        }

        // ---------------- layer 1: K=1280, 40 chunks ------------------------
        const __nv_bfloat16* xh  = g_xhi  + (size_t)btile * 40 * TILEE;
        const __nv_bfloat16* xl  = g_xlo  + (size_t)btile * 40 * TILEE;
        const __nv_bfloat16* w1h = g_w1hi + (size_t)e * 40 * TILEE;
        const __nv_bfloat16* w1o = g_w1lo + (size_t)e * 40 * TILEE;
        ZERO_C();
        if (tid == 0) {
            FILL4(xh, xl, w1h, w1o);
            FILL4(xh + TILEE, xl + TILEE, w1h + TILEE, w1o + TILEE);
        }
        for (int ch = 0; ch < 40; ++ch) {
            if (tid == 0 && ch + 2 < 40) {
                size_t o = (size_t)(ch + 2) * TILEE;
                FILL4(xh + o, xl + o, w1h + o, w1o + o);
            }
            int s_ = cg % 3;
            consume_l1(c, sb, s_, mb0 + s_ * 16, (uint32_t)((cg / 3) & 1),
                       wm, wn, aoff, boff, lane);
            ++cg;
        }

        // producer: prefetch L2 chunks 0,1 (overlaps L1 epilogue)
        const __nv_bfloat16* w2h = g_w2hi + (size_t)e * 4 * TILEE;
        const __nv_bfloat16* w2l = g_w2lo + (size_t)e * 4 * TILEE;
        if (tid == 0) {
            FILL2(w2h, w2l);
            FILL2(w2h + TILEE, w2l + TILEE);
        }
        if (tid != 0) pg += 2;

        // L1 epilogue: +bias +tau*w1last, silu, split -> h tiles (chunk = wn)
#pragma unroll
        for (int mt = 0; mt < 2; ++mt)
#pragma unroll
            for (int nt = 0; nt < 4; ++nt)
#pragma unroll
                for (int pr = 0; pr < 2; ++pr) {
                    int m   = wm * 32 + mt * 16 + pr * 8 + lr;
                    int col = wn * 32 + nt * 8 + lc * 2;
                    float t  = taus[m];
                    float v0 = c[mt][nt][pr * 2]     + b1s[col]     + t * w1l[col];
                    float v1 = c[mt][nt][pr * 2 + 1] + b1s[col + 1] + t * w1l[col + 1];
                    float h0 = v0 / (1.f + __expf(-v0));
                    float h1 = v1 / (1.f + __expf(-v1));
                    uint32_t hip, lop;
                    split_pack(h0, h1, hip, lop);
                    uint32_t byte = (uint32_t)(m * ROWB + (nt * 8 + lc * 2) * 2);
                    *(uint32_t*)(smem + HOF(wn, 0) + byte) = hip;
                    *(uint32_t*)(smem + HOF(wn, 1) + byte) = lop;
                }
        __syncthreads();   // h visible to all warps

        // ---------------- layer 2: K=128, 4 chunks --------------------------
        ZERO_C();
        for (int ch = 0; ch < 4; ++ch) {
            if (tid == 0 && ch + 2 < 4) {
                size_t o = (size_t)(ch + 2) * TILEE;
                FILL2(w2h + o, w2l + o);
            }
            if (tid != 0 && ch + 2 < 4) ++pg;
            int s_ = cg % 3;
            consume_h(c, sb, HOF(ch, 0), HOF(ch, 1), s_, mb0 + s_ * 16,
                      (uint32_t)((cg / 3) & 1), wm, wn, aoff, boff, lane);
            ++cg;
        }
        // all warps must finish reading HOF before the L2 epilogue overwrites
        __syncthreads();

        // producer: prefetch L3 nh=0 chunks 0,1 (overlaps L2 epilogue)
        const __nv_bfloat16* w3h = g_w3hi + (size_t)e * 8 * TILEE;
        const __nv_bfloat16* w3l = g_w3lo + (size_t)e * 8 * TILEE;
        if (tid == 0) {
            FILL2(w3h, w3l);
            FILL2(w3h + TILEE, w3l + TILEE);
        }
        if (tid != 0) pg += 2;

        // L2 epilogue: +bias, silu, *p -> h tiles
#pragma unroll
        for (int mt = 0; mt < 2; ++mt)
#pragma unroll
            for (int nt = 0; nt < 4; ++nt)
#pragma unroll
                for (int pr = 0; pr < 2; ++pr) {
                    int m   = wm * 32 + mt * 16 + pr * 8 + lr;
                    int col = wn * 32 + nt * 8 + lc * 2;
                    float pe = p_hat[(size_t)(b0 + m) * KEXP + e];
                    float v0 = c[mt][nt][pr * 2]     + b2s[col];
                    float v1 = c[mt][nt][pr * 2 + 1] + b2s[col + 1];
                    float h0 = pe * (v0 / (1.f + __expf(-v0)));
                    float h1 = pe * (v1 / (1.f + __expf(-v1)));
                    uint32_t hip, lop;
                    split_pack(h0, h1, hip, lop);
                    uint32_t byte = (uint32_t)(m * ROWB + (nt * 8 + lc * 2) * 2);
                    *(uint32_t*)(smem + HOF(wn, 0) + byte) = hip;
                    *(uint32_t*)(smem + HOF(wn, 1) + byte) = lop;
                }
        __syncthreads();   // new h visible to all warps

        // ---------------- layer 3: two 128-col halves, K=128 ----------------
        for (int nh = 0; nh < 2; ++nh) {
            const __nv_bfloat16* bh = w3h + (size_t)nh * 4 * TILEE;
            const __nv_bfloat16* bl = w3l + (size_t)nh * 4 * TILEE;
            if (nh == 1) {
                if (tid == 0) {
                    FILL2(bh, bl);
                    FILL2(bh + TILEE, bl + TILEE);
                }
                if (tid != 0) pg += 2;
            }
            ZERO_C();
            for (int ch = 0; ch < 4; ++ch) {
                if (tid == 0 && ch + 2 < 4) {
                    size_t o = (size_t)(ch + 2) * TILEE;
                    FILL2(bh + o, bl + o);
                }
                if (tid != 0 && ch + 2 < 4) ++pg;
                int s_ = cg % 3;
                consume_h(c, sb, HOF(ch, 0), HOF(ch, 1), s_, mb0 + s_ * 16,
                          (uint32_t)((cg / 3) & 1), wm, wn, aoff, boff, lane);
                ++cg;
            }
            // epilogue: e==0 -> store c + sum_k p_k*b3_k (init fused);
            //           e>0  -> out += c
            if (e == 0) {
#pragma unroll
                for (int mt = 0; mt < 2; ++mt)
#pragma unroll
                    for (int nt = 0; nt < 4; ++nt)
#pragma unroll
                        for (int pr = 0; pr < 2; ++pr) {
                            int m   = wm * 32 + mt * 16 + pr * 8 + lr;
                            int col = nh * 128 + wn * 32 + nt * 8 + lc * 2;
                            const float* pp = p_hat + (size_t)(b0 + m) * KEXP;
                            float bs0 = 0.f, bs1 = 0.f;
#pragma unroll
                            for (int k = 0; k < KEXP; ++k) {
                                float pk = pp[k];
                                bs0 = fmaf(pk, b3s[k * LAT + col],     bs0);
                                bs1 = fmaf(pk, b3s[k * LAT + col + 1], bs1);
                            }
                            float2 v;
                            v.x = c[mt][nt][pr * 2]     + bs0;
                            v.y = c[mt][nt][pr * 2 + 1] + bs1;
                            *reinterpret_cast<float2*>(
                                out + (size_t)(b0 + m) * LAT + col) = v;
                        }
            } else {
#pragma unroll
                for (int mt = 0; mt < 2; ++mt)
#pragma unroll
                    for (int nt = 0; nt < 4; ++nt)
#pragma unroll
                        for (int pr = 0; pr < 2; ++pr) {
                            int m   = wm * 32 + mt * 16 + pr * 8 + lr;
                            int col = nh * 128 + wn * 32 + nt * 8 + lc * 2;
                            float* o = out + (size_t)(b0 + m) * LAT + col;
                            float2 v = *reinterpret_cast<float2*>(o);
                            v.x += c[mt][nt][pr * 2];
                            v.y += c[mt][nt][pr * 2 + 1];
                            *reinterpret_cast<float2*>(o) = v;
                        }
            }
        }
    }  // experts
}

// ============================== launch ======================================
extern "C" void kernel_launch(void* const* d_in, const int* in_sizes, int n_in,
                              void* d_out, int out_size) {
    const float* cond = (const float*)d_in[0];
    const float* u    = (const float*)d_in[1];
    const float* tau  = (const float*)d_in[2];
    const float* p    = (const float*)d_in[3];
    const float* W1   = (const float*)d_in[4];
    const float* b1   = (const float*)d_in[5];
    const float* W2   = (const float*)d_in[6];
    const float* b2   = (const float*)d_in[7];
    const float* W3   = (const float*)d_in[8];
    const float* b3   = (const float*)d_in[9];
    float* out = (float*)d_out;

    static int configured = 0;
    if (!configured) {
        cudaFuncSetAttribute(phase_moe_mma,
                             cudaFuncAttributeMaxDynamicSharedMemorySize,
                             SMEM_TOTAL);
        configured = 1;
    }

    convert_x_kernel<<<8192, 256>>>(u, cond);
    convert_w_kernel<<<2048, 256>>>(W1, W2, W3);
    phase_moe_mma<<<B_TOK / 128, 512, SMEM_TOTAL>>>(tau, p, W1, b1, b2, b3, out);
}

// round 15
// speedup vs baseline: 1.0195x; 1.0195x over previous
#include <cuda_runtime.h>
#include <cuda_bf16.h>
#include <cstdint>

// ============================================================================
// PhaseMoE via mma.sync (HMMA m16n8k16 bf16), hi/lo 3-MMA split.
// R14 = R12 pipeline (proven best main kernel) + fused init_out (from R13)
// + vectorized tile-structured convert_x (was 118us at 3.5TB/s with
// per-element div/branch/2B stores; now float4 loads + uint4 stores).
// mma_burst REVERTED to R12 order (R13 reorder regressed ~30us).
// 512 threads, 4x4 warp grid, 32x32 warp tile.
// ============================================================================

#define B_TOK 32768
#define KEXP  8
#define EIN   1280
#define HID   128
#define LAT   256

#define ROWB   80
#define TILEB  (128 * ROWB)     // 10240 B per 128x32 tile
#define TILEE  (128 * 40)       // 5120 bf16 elems per padded tile

// smem map: 3 stage buffers x 4 tiles, 4 h-chunks x hi/lo, aux, b3
#define STG(s, t) ((uint32_t)(((s) * 4 + (t)) * TILEB))   // t:0 Ahi 1 Alo 2 Bhi 3 Blo
#define HOF(c, h) ((uint32_t)((12 + (c) * 2 + (h)) * TILEB))
#define AUX       ((uint32_t)(20 * TILEB))
#define B3OFF     (AUX + 4096)
#define SMEM_TOTAL (20 * TILEB + 4096 + 8192)

// ---- pre-tiled bf16 hi/lo scratch (__device__ globals) ----
__device__ __align__(16) __nv_bfloat16 g_xhi[(size_t)256 * 40 * TILEE];
__device__ __align__(16) __nv_bfloat16 g_xlo[(size_t)256 * 40 * TILEE];
__device__ __align__(16) __nv_bfloat16 g_w1hi[KEXP * 40 * TILEE];
__device__ __align__(16) __nv_bfloat16 g_w1lo[KEXP * 40 * TILEE];
__device__ __align__(16) __nv_bfloat16 g_w2hi[KEXP * 4 * TILEE];
__device__ __align__(16) __nv_bfloat16 g_w2lo[KEXP * 4 * TILEE];
__device__ __align__(16) __nv_bfloat16 g_w3hi[KEXP * 2 * 4 * TILEE];
__device__ __align__(16) __nv_bfloat16 g_w3lo[KEXP * 2 * 4 * TILEE];

// ============================ helpers =======================================
__device__ __forceinline__ uint32_t smem_u32(const void* p) {
    uint32_t a;
    asm("{ .reg .u64 t; cvta.to.shared.u64 t, %1; cvt.u32.u64 %0, t; }"
        : "=r"(a) : "l"(p));
    return a;
}
#define MBAR_INIT(mb, c) asm volatile("mbarrier.init.shared.b64 [%0], %1;" :: "r"(mb), "r"(c) : "memory")
#define MBAR_EXPECT_TX(mb, tx) asm volatile("mbarrier.arrive.expect_tx.shared.b64 _, [%0], %1;" :: "r"(mb), "r"(tx) : "memory")
#define MBAR_ARRIVE(mb) asm volatile("mbarrier.arrive.shared.b64 _, [%0];" :: "r"(mb) : "memory")

__device__ __forceinline__ void bulk_g2s(uint32_t dst, const void* src,
                                         uint32_t bytes, uint32_t mb) {
    asm volatile(
        "cp.async.bulk.shared::cta.global.mbarrier::complete_tx::bytes "
        "[%0], [%1], %2, [%3];"
        :: "r"(dst), "l"(src), "r"(bytes), "r"(mb) : "memory");
}

__device__ __forceinline__ void mbar_wait(uint32_t mb, uint32_t parity) {
    asm volatile(
        "{\n\t.reg .pred P1;\n\t"
        "WAIT_%=:\n\t"
        "mbarrier.try_wait.parity.acquire.cta.shared::cta.b64 P1, [%0], %1, 0x989680;\n\t"
        "@P1 bra.uni DONE_%=;\n\t"
        "bra.uni WAIT_%=;\n\t"
        "DONE_%=:\n\t}"
        :: "r"(mb), "r"(parity) : "memory");
}

__device__ __forceinline__ void ldsm4(uint32_t addr, uint32_t* r) {
    asm volatile("ldmatrix.sync.aligned.m8n8.x4.shared.b16 {%0,%1,%2,%3}, [%4];"
                 : "=r"(r[0]), "=r"(r[1]), "=r"(r[2]), "=r"(r[3]) : "r"(addr));
}

__device__ __forceinline__ void mma16816(float* c, const uint32_t* a,
                                         uint32_t b0, uint32_t b1) {
    asm volatile(
        "mma.sync.aligned.m16n8k16.row.col.f32.bf16.bf16.f32 "
        "{%0,%1,%2,%3}, {%4,%5,%6,%7}, {%8,%9}, {%0,%1,%2,%3};"
        : "+f"(c[0]), "+f"(c[1]), "+f"(c[2]), "+f"(c[3])
        : "r"(a[0]), "r"(a[1]), "r"(a[2]), "r"(a[3]), "r"(b0), "r"(b1));
}

// MMA burst (R12 ordering — measured best)
__device__ __forceinline__ void mma_burst(float c[2][4][4],
        uint32_t ah[2][2][4], uint32_t al[2][2][4],
        uint32_t bh[2][2][4], uint32_t bl[2][2][4]) {
#pragma unroll
    for (int ks = 0; ks < 2; ++ks)
#pragma unroll
        for (int mt = 0; mt < 2; ++mt)
#pragma unroll
            for (int nt = 0; nt < 4; ++nt) {
                int pr = nt >> 1, hf = (nt & 1) * 2;
                mma16816(c[mt][nt], ah[ks][mt], bh[ks][pr][hf], bh[ks][pr][hf + 1]);
                mma16816(c[mt][nt], ah[ks][mt], bl[ks][pr][hf], bl[ks][pr][hf + 1]);
                mma16816(c[mt][nt], al[ks][mt], bh[ks][pr][hf], bh[ks][pr][hf + 1]);
            }
}

// L1 consume: A and B both live in the stage ring.
__device__ __forceinline__ void consume_l1(float c[2][4][4], uint32_t sb,
        int s, uint32_t fb, uint32_t parity,
        int wm, int wn, uint32_t aoff, uint32_t boff, int lane) {
    mbar_wait(fb, parity);
    uint32_t ah[2][2][4], al[2][2][4], bh[2][2][4], bl[2][2][4];
#pragma unroll
    for (int ks = 0; ks < 2; ++ks) {
#pragma unroll
        for (int mt = 0; mt < 2; ++mt) {
            uint32_t base = (uint32_t)((wm * 32 + mt * 16) * ROWB + ks * 32) + aoff;
            ldsm4(sb + STG(s, 0) + base, ah[ks][mt]);
            ldsm4(sb + STG(s, 1) + base, al[ks][mt]);
        }
#pragma unroll
        for (int pr = 0; pr < 2; ++pr) {
            uint32_t base = (uint32_t)((wn * 32 + pr * 16) * ROWB + ks * 32) + boff;
            ldsm4(sb + STG(s, 2) + base, bh[ks][pr]);
            ldsm4(sb + STG(s, 3) + base, bl[ks][pr]);
        }
    }
    __syncwarp();
    if (lane == 0) MBAR_ARRIVE(fb + 8);   // smem free; MMAs read registers
    mma_burst(c, ah, al, bh, bl);
}

// L2/L3 consume: A in HOF (stable), B in the stage ring.
__device__ __forceinline__ void consume_h(float c[2][4][4], uint32_t sb,
        uint32_t Ahi, uint32_t Alo, int s, uint32_t fb, uint32_t parity,
        int wm, int wn, uint32_t aoff, uint32_t boff, int lane) {
    uint32_t ah[2][2][4], al[2][2][4], bh[2][2][4], bl[2][2][4];
#pragma unroll
    for (int ks = 0; ks < 2; ++ks)
#pragma unroll
        for (int mt = 0; mt < 2; ++mt) {
            uint32_t base = (uint32_t)((wm * 32 + mt * 16) * ROWB + ks * 32) + aoff;
            ldsm4(sb + Ahi + base, ah[ks][mt]);
            ldsm4(sb + Alo + base, al[ks][mt]);
        }
    mbar_wait(fb, parity);
#pragma unroll
    for (int ks = 0; ks < 2; ++ks)
#pragma unroll
        for (int pr = 0; pr < 2; ++pr) {
            uint32_t base = (uint32_t)((wn * 32 + pr * 16) * ROWB + ks * 32) + boff;
            ldsm4(sb + STG(s, 2) + base, bh[ks][pr]);
            ldsm4(sb + STG(s, 3) + base, bl[ks][pr]);
        }
    __syncwarp();
    if (lane == 0) MBAR_ARRIVE(fb + 8);
    mma_burst(c, ah, al, bh, bl);
}

__device__ __forceinline__ void split_pack(float h0, float h1,
                                           uint32_t& hip, uint32_t& lop) {
    __nv_bfloat16 h0h = __float2bfloat16(h0);
    __nv_bfloat16 h1h = __float2bfloat16(h1);
    hip = (uint32_t)__bfloat16_as_ushort(h0h) |
          ((uint32_t)__bfloat16_as_ushort(h1h) << 16);
    lop = (uint32_t)__bfloat16_as_ushort(__float2bfloat16(h0 - __bfloat162float(h0h))) |
          ((uint32_t)__bfloat16_as_ushort(__float2bfloat16(h1 - __bfloat162float(h1h))) << 16);
}

#define ZERO_C() do { \
    _Pragma("unroll") for (int mt = 0; mt < 2; ++mt) \
    _Pragma("unroll") for (int nt = 0; nt < 4; ++nt) \
    _Pragma("unroll") for (int q = 0; q < 4; ++q) c[mt][nt][q] = 0.f; } while (0)

// ======================= prep kernels (tiled layout) ========================
// Tile-structured convert_x: one block per (token-tile, chunk). Each thread
// converts 16 contiguous source floats (4x float4, coalesced) and writes
// 2x uint4 to hi and lo (16B stores). No div, no per-element branch.
// A 16-elem span never straddles u/cond (256 % 16 == 0). Padding (bytes
// 64..79 of each 80B row) is never read by ldsm -> left unwritten.
__global__ void convert_x_kernel(const float* __restrict__ u,
                                 const float* __restrict__ cond) {
    int blk  = blockIdx.x;          // 256*40 blocks
    int tile = blk / 40, ch = blk % 40;
    int t    = threadIdx.x;         // 256 threads
    int row  = t >> 1;              // 0..127
    int half = t & 1;               // 16 elems per half
    int gtok = tile * 128 + row;
    int col0 = ch * 32 + half * 16;

    const float* src = (col0 < 256)
        ? u    + (size_t)gtok * 256  + col0
        : cond + (size_t)gtok * 1024 + (col0 - 256);

    float f[16];
#pragma unroll
    for (int i = 0; i < 4; ++i) {
        float4 v = *reinterpret_cast<const float4*>(src + i * 4);
        f[i * 4 + 0] = v.x; f[i * 4 + 1] = v.y;
        f[i * 4 + 2] = v.z; f[i * 4 + 3] = v.w;
    }
    uint32_t hi[8], lo[8];
#pragma unroll
    for (int j = 0; j < 8; ++j)
        split_pack(f[j * 2], f[j * 2 + 1], hi[j], lo[j]);

    size_t dstE = ((size_t)(tile * 40 + ch) * 128 + row) * 40 + half * 16;
    uint4* dh = reinterpret_cast<uint4*>(g_xhi + dstE);
    uint4* dl = reinterpret_cast<uint4*>(g_xlo + dstE);
    const uint4* sh = reinterpret_cast<const uint4*>(hi);
    const uint4* sl = reinterpret_cast<const uint4*>(lo);
    dh[0] = sh[0]; dh[1] = sh[1];
    dl[0] = sl[0]; dl[1] = sl[1];
}

__global__ void convert_w_kernel(const float* __restrict__ W1,
                                 const float* __restrict__ W2,
                                 const float* __restrict__ W3) {
    const int N1 = KEXP * HID * EIN;
    const int N2 = KEXP * HID * HID;
    const int N3 = KEXP * LAT * HID;
    const int total = N1 + N2 + N3;
    for (int i = blockIdx.x * blockDim.x + threadIdx.x; i < total;
         i += gridDim.x * blockDim.x) {
        float v;
        size_t dst;
        __nv_bfloat16 *dh, *dl;
        if (i < N1) {
            int e = i / (HID * EIN), r = i - e * (HID * EIN);
            int n = r / EIN, k = r - n * EIN;
            int c = k >> 5, kk = k & 31;
            v = W1[((size_t)e * 1281 + k) * HID + n];
            dst = ((size_t)(e * 40 + c) * 128 + n) * 40 + kk;
            dh = g_w1hi; dl = g_w1lo;
        } else if (i < N1 + N2) {
            int j = i - N1;
            int e = j / (HID * HID), r = j - e * (HID * HID);
            int n = r / HID, k = r - n * HID;
            int c = k >> 5, kk = k & 31;
            v = W2[((size_t)e * HID + k) * HID + n];
            dst = ((size_t)(e * 4 + c) * 128 + n) * 40 + kk;
            dh = g_w2hi; dl = g_w2lo;
        } else {
            int j = i - N1 - N2;
            int e = j / (LAT * HID), r = j - e * (LAT * HID);
            int n = r / HID, k = r - n * HID;
            int nh = n >> 7, nn = n & 127, c = k >> 5, kk = k & 31;
            v = W3[((size_t)e * HID + k) * LAT + n];
            dst = ((size_t)((e * 2 + nh) * 4 + c) * 128 + nn) * 40 + kk;
            dh = g_w3hi; dl = g_w3lo;
        }
        __nv_bfloat16 hi = __float2bfloat16(v);
        dh[dst] = hi;
        dl[dst] = __float2bfloat16(v - __bfloat162float(hi));
    }
}

// =========================== main kernel ====================================
#define FILL4(xh_, xl_, wh_, wl_) do { \
    int s_ = pg % 3; uint32_t par_ = (uint32_t)(((pg / 3) + 1) & 1); \
    uint32_t fb_ = mb0 + s_ * 16, eb_ = fb_ + 8; \
    mbar_wait(eb_, par_); \
    MBAR_EXPECT_TX(fb_, 4 * TILEB); \
    bulk_g2s(sb + STG(s_, 0), (xh_), TILEB, fb_); \
    bulk_g2s(sb + STG(s_, 1), (xl_), TILEB, fb_); \
    bulk_g2s(sb + STG(s_, 2), (wh_), TILEB, fb_); \
    bulk_g2s(sb + STG(s_, 3), (wl_), TILEB, fb_); \
    ++pg; } while (0)

#define FILL2(wh_, wl_) do { \
    int s_ = pg % 3; uint32_t par_ = (uint32_t)(((pg / 3) + 1) & 1); \
    uint32_t fb_ = mb0 + s_ * 16, eb_ = fb_ + 8; \
    mbar_wait(eb_, par_); \
    MBAR_EXPECT_TX(fb_, 2 * TILEB); \
    bulk_g2s(sb + STG(s_, 2), (wh_), TILEB, fb_); \
    bulk_g2s(sb + STG(s_, 3), (wl_), TILEB, fb_); \
    ++pg; } while (0)

__global__ __launch_bounds__(512, 1)
void phase_moe_mma(const float* __restrict__ tau,
                   const float* __restrict__ p_hat,
                   const float* __restrict__ W1,
                   const float* __restrict__ b1,
                   const float* __restrict__ b2,
                   const float* __restrict__ b3,
                   float* __restrict__ out) {
    extern __shared__ __align__(128) char smem[];
    const uint32_t sb = smem_u32(smem);
    const int tid  = threadIdx.x;
    const int lane = tid & 31;
    const int w    = tid >> 5;
    const int wm   = w >> 2, wn = w & 3;
    const int lr   = lane >> 2, lc = lane & 3;
    const int b0   = blockIdx.x * 128;
    const int btile = blockIdx.x;

    const uint32_t aoff = (uint32_t)(((lane & 7) + ((lane >> 3) & 1) * 8) * ROWB
                                     + ((lane >> 4) & 1) * 16);
    const uint32_t boff = (uint32_t)(((lane & 7) + ((lane >> 4) & 1) * 8) * ROWB
                                     + ((lane >> 3) & 1) * 16);

    float* b1s  = reinterpret_cast<float*>(smem + AUX);          // 128
    float* b2s  = reinterpret_cast<float*>(smem + AUX + 512);    // 128
    float* w1l  = reinterpret_cast<float*>(smem + AUX + 1024);   // 128
    float* taus = reinterpret_cast<float*>(smem + AUX + 1536);   // 128
    float* b3s  = reinterpret_cast<float*>(smem + B3OFF);        // 8*256
    const uint32_t mb0 = sb + AUX + 2048;                        // 3x(full,empty)

    if (tid == 0) {
#pragma unroll
        for (int s = 0; s < 3; ++s) {
            MBAR_INIT(mb0 + s * 16,     1);    // full: expect_tx arrival
            MBAR_INIT(mb0 + s * 16 + 8, 16);   // empty: one arrive per warp
        }
    }
    if (tid < 128) taus[tid] = tau[b0 + tid];
    for (int i = tid; i < KEXP * LAT; i += 512) b3s[i] = b3[i];
    __syncthreads();   // mbarrier init + b3s visible

    int pg = 0;   // producer fill counter (tid0)
    int cg = 0;   // consumer counter (all threads)
    float c[2][4][4];

    for (int e = 0; e < KEXP; ++e) {
        __syncthreads();   // bias smem reuse safe; h tiles free
        if (tid < 128) {
            b1s[tid] = b1[e * HID + tid];
            b2s[tid] = b2[e * HID + tid];
            w1l[tid] = W1[((size_t)e * 1281 + 1280) * HID + tid];
        }

        // ---------------- layer 1: K=1280, 40 chunks ------------------------
        const __nv_bfloat16* xh  = g_xhi  + (size_t)btile * 40 * TILEE;
        const __nv_bfloat16* xl  = g_xlo  + (size_t)btile * 40 * TILEE;
        const __nv_bfloat16* w1h = g_w1hi + (size_t)e * 40 * TILEE;
        const __nv_bfloat16* w1o = g_w1lo + (size_t)e * 40 * TILEE;
        ZERO_C();
        if (tid == 0) {
            FILL4(xh, xl, w1h, w1o);
            FILL4(xh + TILEE, xl + TILEE, w1h + TILEE, w1o + TILEE);
        }
        for (int ch = 0; ch < 40; ++ch) {
            if (tid == 0 && ch + 2 < 40) {
                size_t o = (size_t)(ch + 2) * TILEE;
                FILL4(xh + o, xl + o, w1h + o, w1o + o);
            }
            int s_ = cg % 3;
            consume_l1(c, sb, s_, mb0 + s_ * 16, (uint32_t)((cg / 3) & 1),
                       wm, wn, aoff, boff, lane);
            ++cg;
        }

        // producer: prefetch L2 chunks 0,1 (overlaps L1 epilogue)
        const __nv_bfloat16* w2h = g_w2hi + (size_t)e * 4 * TILEE;
        const __nv_bfloat16* w2l = g_w2lo + (size_t)e * 4 * TILEE;
        if (tid == 0) {
            FILL2(w2h, w2l);
            FILL2(w2h + TILEE, w2l + TILEE);
        }
        if (tid != 0) pg += 2;

        // L1 epilogue: +bias +tau*w1last, silu, split -> h tiles (chunk = wn)
#pragma unroll
        for (int mt = 0; mt < 2; ++mt)
#pragma unroll
            for (int nt = 0; nt < 4; ++nt)
#pragma unroll
                for (int pr = 0; pr < 2; ++pr) {
                    int m   = wm * 32 + mt * 16 + pr * 8 + lr;
                    int col = wn * 32 + nt * 8 + lc * 2;
                    float t  = taus[m];
                    float v0 = c[mt][nt][pr * 2]     + b1s[col]     + t * w1l[col];
                    float v1 = c[mt][nt][pr * 2 + 1] + b1s[col + 1] + t * w1l[col + 1];
                    float h0 = v0 / (1.f + __expf(-v0));
                    float h1 = v1 / (1.f + __expf(-v1));
                    uint32_t hip, lop;
                    split_pack(h0, h1, hip, lop);
                    uint32_t byte = (uint32_t)(m * ROWB + (nt * 8 + lc * 2) * 2);
                    *(uint32_t*)(smem + HOF(wn, 0) + byte) = hip;
                    *(uint32_t*)(smem + HOF(wn, 1) + byte) = lop;
                }
        __syncthreads();   // h visible to all warps

        // ---------------- layer 2: K=128, 4 chunks --------------------------
        ZERO_C();
        for (int ch = 0; ch < 4; ++ch) {
            if (tid == 0 && ch + 2 < 4) {
                size_t o = (size_t)(ch + 2) * TILEE;
                FILL2(w2h + o, w2l + o);
            }
            if (tid != 0 && ch + 2 < 4) ++pg;
            int s_ = cg % 3;
            consume_h(c, sb, HOF(ch, 0), HOF(ch, 1), s_, mb0 + s_ * 16,
                      (uint32_t)((cg / 3) & 1), wm, wn, aoff, boff, lane);
            ++cg;
        }
        // all warps must finish reading HOF before the L2 epilogue overwrites
        __syncthreads();

        // producer: prefetch L3 nh=0 chunks 0,1 (overlaps L2 epilogue)
        const __nv_bfloat16* w3h = g_w3hi + (size_t)e * 8 * TILEE;
        const __nv_bfloat16* w3l = g_w3lo + (size_t)e * 8 * TILEE;
        if (tid == 0) {
            FILL2(w3h, w3l);
            FILL2(w3h + TILEE, w3l + TILEE);
        }
        if (tid != 0) pg += 2;

        // L2 epilogue: +bias, silu, *p -> h tiles
#pragma unroll
        for (int mt = 0; mt < 2; ++mt)
#pragma unroll
            for (int nt = 0; nt < 4; ++nt)
#pragma unroll
                for (int pr = 0; pr < 2; ++pr) {
                    int m   = wm * 32 + mt * 16 + pr * 8 + lr;
                    int col = wn * 32 + nt * 8 + lc * 2;
                    float pe = p_hat[(size_t)(b0 + m) * KEXP + e];
                    float v0 = c[mt][nt][pr * 2]     + b2s[col];
                    float v1 = c[mt][nt][pr * 2 + 1] + b2s[col + 1];
                    float h0 = pe * (v0 / (1.f + __expf(-v0)));
                    float h1 = pe * (v1 / (1.f + __expf(-v1)));
                    uint32_t hip, lop;
                    split_pack(h0, h1, hip, lop);
                    uint32_t byte = (uint32_t)(m * ROWB + (nt * 8 + lc * 2) * 2);
                    *(uint32_t*)(smem + HOF(wn, 0) + byte) = hip;
                    *(uint32_t*)(smem + HOF(wn, 1) + byte) = lop;
                }
        __syncthreads();   // new h visible to all warps

        // ---------------- layer 3: two 128-col halves, K=128 ----------------
        for (int nh = 0; nh < 2; ++nh) {
            const __nv_bfloat16* bh = w3h + (size_t)nh * 4 * TILEE;
            const __nv_bfloat16* bl = w3l + (size_t)nh * 4 * TILEE;
            if (nh == 1) {
                if (tid == 0) {
                    FILL2(bh, bl);
                    FILL2(bh + TILEE, bl + TILEE);
                }
                if (tid != 0) pg += 2;
            }
            ZERO_C();
            for (int ch = 0; ch < 4; ++ch) {
                if (tid == 0 && ch + 2 < 4) {
                    size_t o = (size_t)(ch + 2) * TILEE;
                    FILL2(bh + o, bl + o);
                }
                if (tid != 0 && ch + 2 < 4) ++pg;
                int s_ = cg % 3;
                consume_h(c, sb, HOF(ch, 0), HOF(ch, 1), s_, mb0 + s_ * 16,
                          (uint32_t)((cg / 3) & 1), wm, wn, aoff, boff, lane);
                ++cg;
            }
            // epilogue: e==0 -> store c + sum_k p_k*b3_k (init fused);
            //           e>0  -> out += c
            if (e == 0) {
#pragma unroll
                for (int mt = 0; mt < 2; ++mt)
#pragma unroll
                    for (int nt = 0; nt < 4; ++nt)
#pragma unroll
                        for (int pr = 0; pr < 2; ++pr) {
                            int m   = wm * 32 + mt * 16 + pr * 8 + lr;
                            int col = nh * 128 + wn * 32 + nt * 8 + lc * 2;
                            const float* pp = p_hat + (size_t)(b0 + m) * KEXP;
                            float bs0 = 0.f, bs1 = 0.f;
#pragma unroll
                            for (int k = 0; k < KEXP; ++k) {
                                float pk = pp[k];
                                bs0 = fmaf(pk, b3s[k * LAT + col],     bs0);
                                bs1 = fmaf(pk, b3s[k * LAT + col + 1], bs1);
                            }
                            float2 v;
                            v.x = c[mt][nt][pr * 2]     + bs0;
                            v.y = c[mt][nt][pr * 2 + 1] + bs1;
                            *reinterpret_cast<float2*>(
                                out + (size_t)(b0 + m) * LAT + col) = v;
                        }
            } else {
#pragma unroll
                for (int mt = 0; mt < 2; ++mt)
#pragma unroll
                    for (int nt = 0; nt < 4; ++nt)
#pragma unroll
                        for (int pr = 0; pr < 2; ++pr) {
                            int m   = wm * 32 + mt * 16 + pr * 8 + lr;
                            int col = nh * 128 + wn * 32 + nt * 8 + lc * 2;
                            float* o = out + (size_t)(b0 + m) * LAT + col;
                            float2 v = *reinterpret_cast<float2*>(o);
                            v.x += c[mt][nt][pr * 2];
                            v.y += c[mt][nt][pr * 2 + 1];
                            *reinterpret_cast<float2*>(o) = v;
                        }
            }
        }
    }  // experts
}

// ============================== launch ======================================
extern "C" void kernel_launch(void* const* d_in, const int* in_sizes, int n_in,
                              void* d_out, int out_size) {
    const float* cond = (const float*)d_in[0];
    const float* u    = (const float*)d_in[1];
    const float* tau  = (const float*)d_in[2];
    const float* p    = (const float*)d_in[3];
    const float* W1   = (const float*)d_in[4];
    const float* b1   = (const float*)d_in[5];
    const float* W2   = (const float*)d_in[6];
    const float* b2   = (const float*)d_in[7];
    const float* W3   = (const float*)d_in[8];
    const float* b3   = (const float*)d_in[9];
    float* out = (float*)d_out;

    static int configured = 0;
    if (!configured) {
        cudaFuncSetAttribute(phase_moe_mma,
                             cudaFuncAttributeMaxDynamicSharedMemorySize,
                             SMEM_TOTAL);
        configured = 1;
    }

    convert_x_kernel<<<256 * 40, 256>>>(u, cond);
    convert_w_kernel<<<2048, 256>>>(W1, W2, W3);
    phase_moe_mma<<<B_TOK / 128, 512, SMEM_TOTAL>>>(tau, p, W1, b1, b2, b3, out);
}

// round 16
// speedup vs baseline: 1.0690x; 1.0485x over previous
#include <cuda_runtime.h>
#include <cuda_bf16.h>
#include <cstdint>

// ============================================================================
// PhaseMoE via mma.sync (HMMA m16n8k16 bf16), hi/lo 3-MMA split.
// R15 = exact R12 main kernel (measured 1040us: de-phased consume, separate
// init_out, RMW epilogue) + fast convert_x (R14) + NEW vectorized convert_w
// (smem-transpose tiles, coalesced loads, 16B stores; was 31us scalar).
// Ledger: fused-init variant cost main ~+50us -> unfused restored.
// 512 threads, 4x4 warp grid, 32x32 warp tile.
// ============================================================================

#define B_TOK 32768
#define KEXP  8
#define EIN   1280
#define HID   128
#define LAT   256

#define ROWB   80
#define TILEB  (128 * ROWB)     // 10240 B per 128x32 tile
#define TILEE  (128 * 40)       // 5120 bf16 elems per padded tile

// smem map: 3 stage buffers x 4 tiles, 4 h-chunks x hi/lo, aux
#define STG(s, t) ((uint32_t)(((s) * 4 + (t)) * TILEB))   // t:0 Ahi 1 Alo 2 Bhi 3 Blo
#define HOF(c, h) ((uint32_t)((12 + (c) * 2 + (h)) * TILEB))
#define AUX       ((uint32_t)(20 * TILEB))
#define SMEM_TOTAL (20 * TILEB + 4096)

// ---- pre-tiled bf16 hi/lo scratch (__device__ globals) ----
__device__ __align__(16) __nv_bfloat16 g_xhi[(size_t)256 * 40 * TILEE];
__device__ __align__(16) __nv_bfloat16 g_xlo[(size_t)256 * 40 * TILEE];
__device__ __align__(16) __nv_bfloat16 g_w1hi[KEXP * 40 * TILEE];
__device__ __align__(16) __nv_bfloat16 g_w1lo[KEXP * 40 * TILEE];
__device__ __align__(16) __nv_bfloat16 g_w2hi[KEXP * 4 * TILEE];
__device__ __align__(16) __nv_bfloat16 g_w2lo[KEXP * 4 * TILEE];
__device__ __align__(16) __nv_bfloat16 g_w3hi[KEXP * 2 * 4 * TILEE];
__device__ __align__(16) __nv_bfloat16 g_w3lo[KEXP * 2 * 4 * TILEE];

// ============================ helpers =======================================
__device__ __forceinline__ uint32_t smem_u32(const void* p) {
    uint32_t a;
    asm("{ .reg .u64 t; cvta.to.shared.u64 t, %1; cvt.u32.u64 %0, t; }"
        : "=r"(a) : "l"(p));
    return a;
}
#define MBAR_INIT(mb, c) asm volatile("mbarrier.init.shared.b64 [%0], %1;" :: "r"(mb), "r"(c) : "memory")
#define MBAR_EXPECT_TX(mb, tx) asm volatile("mbarrier.arrive.expect_tx.shared.b64 _, [%0], %1;" :: "r"(mb), "r"(tx) : "memory")
#define MBAR_ARRIVE(mb) asm volatile("mbarrier.arrive.shared.b64 _, [%0];" :: "r"(mb) : "memory")

__device__ __forceinline__ void bulk_g2s(uint32_t dst, const void* src,
                                         uint32_t bytes, uint32_t mb) {
    asm volatile(
        "cp.async.bulk.shared::cta.global.mbarrier::complete_tx::bytes "
        "[%0], [%1], %2, [%3];"
        :: "r"(dst), "l"(src), "r"(bytes), "r"(mb) : "memory");
}

__device__ __forceinline__ void mbar_wait(uint32_t mb, uint32_t parity) {
    asm volatile(
        "{\n\t.reg .pred P1;\n\t"
        "WAIT_%=:\n\t"
        "mbarrier.try_wait.parity.acquire.cta.shared::cta.b64 P1, [%0], %1, 0x989680;\n\t"
        "@P1 bra.uni DONE_%=;\n\t"
        "bra.uni WAIT_%=;\n\t"
        "DONE_%=:\n\t}"
        :: "r"(mb), "r"(parity) : "memory");
}

__device__ __forceinline__ void ldsm4(uint32_t addr, uint32_t* r) {
    asm volatile("ldmatrix.sync.aligned.m8n8.x4.shared.b16 {%0,%1,%2,%3}, [%4];"
                 : "=r"(r[0]), "=r"(r[1]), "=r"(r[2]), "=r"(r[3]) : "r"(addr));
}

__device__ __forceinline__ void mma16816(float* c, const uint32_t* a,
                                         uint32_t b0, uint32_t b1) {
    asm volatile(
        "mma.sync.aligned.m16n8k16.row.col.f32.bf16.bf16.f32 "
        "{%0,%1,%2,%3}, {%4,%5,%6,%7}, {%8,%9}, {%0,%1,%2,%3};"
        : "+f"(c[0]), "+f"(c[1]), "+f"(c[2]), "+f"(c[3])
        : "r"(a[0]), "r"(a[1]), "r"(a[2]), "r"(a[3]), "r"(b0), "r"(b1));
}

// MMA burst (R12 ordering — measured best)
__device__ __forceinline__ void mma_burst(float c[2][4][4],
        uint32_t ah[2][2][4], uint32_t al[2][2][4],
        uint32_t bh[2][2][4], uint32_t bl[2][2][4]) {
#pragma unroll
    for (int ks = 0; ks < 2; ++ks)
#pragma unroll
        for (int mt = 0; mt < 2; ++mt)
#pragma unroll
            for (int nt = 0; nt < 4; ++nt) {
                int pr = nt >> 1, hf = (nt & 1) * 2;
                mma16816(c[mt][nt], ah[ks][mt], bh[ks][pr][hf], bh[ks][pr][hf + 1]);
                mma16816(c[mt][nt], ah[ks][mt], bl[ks][pr][hf], bl[ks][pr][hf + 1]);
                mma16816(c[mt][nt], al[ks][mt], bh[ks][pr][hf], bh[ks][pr][hf + 1]);
            }
}

// L1 consume: A and B both live in the stage ring.
__device__ __forceinline__ void consume_l1(float c[2][4][4], uint32_t sb,
        int s, uint32_t fb, uint32_t parity,
        int wm, int wn, uint32_t aoff, uint32_t boff, int lane) {
    mbar_wait(fb, parity);
    uint32_t ah[2][2][4], al[2][2][4], bh[2][2][4], bl[2][2][4];
#pragma unroll
    for (int ks = 0; ks < 2; ++ks) {
#pragma unroll
        for (int mt = 0; mt < 2; ++mt) {
            uint32_t base = (uint32_t)((wm * 32 + mt * 16) * ROWB + ks * 32) + aoff;
            ldsm4(sb + STG(s, 0) + base, ah[ks][mt]);
            ldsm4(sb + STG(s, 1) + base, al[ks][mt]);
        }
#pragma unroll
        for (int pr = 0; pr < 2; ++pr) {
            uint32_t base = (uint32_t)((wn * 32 + pr * 16) * ROWB + ks * 32) + boff;
            ldsm4(sb + STG(s, 2) + base, bh[ks][pr]);
            ldsm4(sb + STG(s, 3) + base, bl[ks][pr]);
        }
    }
    __syncwarp();
    if (lane == 0) MBAR_ARRIVE(fb + 8);   // smem free; MMAs read registers
    mma_burst(c, ah, al, bh, bl);
}

// L2/L3 consume: A in HOF (stable), B in the stage ring.
__device__ __forceinline__ void consume_h(float c[2][4][4], uint32_t sb,
        uint32_t Ahi, uint32_t Alo, int s, uint32_t fb, uint32_t parity,
        int wm, int wn, uint32_t aoff, uint32_t boff, int lane) {
    uint32_t ah[2][2][4], al[2][2][4], bh[2][2][4], bl[2][2][4];
#pragma unroll
    for (int ks = 0; ks < 2; ++ks)
#pragma unroll
        for (int mt = 0; mt < 2; ++mt) {
            uint32_t base = (uint32_t)((wm * 32 + mt * 16) * ROWB + ks * 32) + aoff;
            ldsm4(sb + Ahi + base, ah[ks][mt]);
            ldsm4(sb + Alo + base, al[ks][mt]);
        }
    mbar_wait(fb, parity);
#pragma unroll
    for (int ks = 0; ks < 2; ++ks)
#pragma unroll
        for (int pr = 0; pr < 2; ++pr) {
            uint32_t base = (uint32_t)((wn * 32 + pr * 16) * ROWB + ks * 32) + boff;
            ldsm4(sb + STG(s, 2) + base, bh[ks][pr]);
            ldsm4(sb + STG(s, 3) + base, bl[ks][pr]);
        }
    __syncwarp();
    if (lane == 0) MBAR_ARRIVE(fb + 8);
    mma_burst(c, ah, al, bh, bl);
}

__device__ __forceinline__ void split_pack(float h0, float h1,
                                           uint32_t& hip, uint32_t& lop) {
    __nv_bfloat16 h0h = __float2bfloat16(h0);
    __nv_bfloat16 h1h = __float2bfloat16(h1);
    hip = (uint32_t)__bfloat16_as_ushort(h0h) |
          ((uint32_t)__bfloat16_as_ushort(h1h) << 16);
    lop = (uint32_t)__bfloat16_as_ushort(__float2bfloat16(h0 - __bfloat162float(h0h))) |
          ((uint32_t)__bfloat16_as_ushort(__float2bfloat16(h1 - __bfloat162float(h1h))) << 16);
}

#define ZERO_C() do { \
    _Pragma("unroll") for (int mt = 0; mt < 2; ++mt) \
    _Pragma("unroll") for (int nt = 0; nt < 4; ++nt) \
    _Pragma("unroll") for (int q = 0; q < 4; ++q) c[mt][nt][q] = 0.f; } while (0)

// ======================= prep kernels (tiled layout) ========================
// convert_x: one block per (token-tile, chunk); 4x float4 loads, 2x uint4
// stores per target. Padding bytes 64..79 per 80B row never read by ldsm.
__global__ void convert_x_kernel(const float* __restrict__ u,
                                 const float* __restrict__ cond) {
    int blk  = blockIdx.x;          // 256*40 blocks
    int tile = blk / 40, ch = blk % 40;
    int t    = threadIdx.x;         // 256 threads
    int row  = t >> 1;              // 0..127
    int half = t & 1;               // 16 elems per half
    int gtok = tile * 128 + row;
    int col0 = ch * 32 + half * 16;

    const float* src = (col0 < 256)
        ? u    + (size_t)gtok * 256  + col0
        : cond + (size_t)gtok * 1024 + (col0 - 256);

    float f[16];
#pragma unroll
    for (int i = 0; i < 4; ++i) {
        float4 v = *reinterpret_cast<const float4*>(src + i * 4);
        f[i * 4 + 0] = v.x; f[i * 4 + 1] = v.y;
        f[i * 4 + 2] = v.z; f[i * 4 + 3] = v.w;
    }
    uint32_t hi[8], lo[8];
#pragma unroll
    for (int j = 0; j < 8; ++j)
        split_pack(f[j * 2], f[j * 2 + 1], hi[j], lo[j]);

    size_t dstE = ((size_t)(tile * 40 + ch) * 128 + row) * 40 + half * 16;
    uint4* dh = reinterpret_cast<uint4*>(g_xhi + dstE);
    uint4* dl = reinterpret_cast<uint4*>(g_xlo + dstE);
    const uint4* sh = reinterpret_cast<const uint4*>(hi);
    const uint4* sl = reinterpret_cast<const uint4*>(lo);
    dh[0] = sh[0]; dh[1] = sh[1];
    dl[0] = sl[0]; dl[1] = sl[1];
}

// convert_w: one block per output chunk-tile (W1: 320, W2: 32, W3: 64 blocks).
// Coalesced 32k x 128n f32 loads -> padded smem transpose -> per-thread
// 16-element split -> 2x uint4 stores per target. No div/mod in hot path.
__global__ void convert_w_kernel(const float* __restrict__ W1,
                                 const float* __restrict__ W2,
                                 const float* __restrict__ W3) {
    __shared__ float ts[32][132];   // [k][n], padded vs bank conflicts
    int blk = blockIdx.x;           // 416 total
    const float* src;
    int ldsrc;
    __nv_bfloat16 *dh, *dl;
    size_t dstE;
    if (blk < 320) {                              // W1: e in 0..7, c in 0..39
        int e = blk / 40, cch = blk % 40;
        src   = W1 + ((size_t)e * 1281 + cch * 32) * HID;
        ldsrc = HID;
        dstE  = (size_t)(e * 40 + cch) * 128 * 40;
        dh = g_w1hi; dl = g_w1lo;
    } else if (blk < 352) {                       // W2: e 0..7, c 0..3
        int j = blk - 320, e = j / 4, cch = j % 4;
        src   = W2 + ((size_t)e * HID + cch * 32) * HID;
        ldsrc = HID;
        dstE  = (size_t)(e * 4 + cch) * 128 * 40;
        dh = g_w2hi; dl = g_w2lo;
    } else {                                      // W3: e 0..7, nh 0..1, c 0..3
        int j = blk - 352, e = j / 8, r = j % 8;
        int nh = r / 4, cch = r % 4;
        src   = W3 + ((size_t)e * HID + cch * 32) * LAT + nh * 128;
        ldsrc = LAT;
        dstE  = (size_t)((e * 2 + nh) * 4 + cch) * 128 * 40;
        dh = g_w3hi; dl = g_w3lo;
    }
    int t = threadIdx.x;            // 256
    // coalesced load 32x128 f32
#pragma unroll
    for (int i = 0; i < 16; ++i) {
        int idx = t + i * 256;
        int k = idx >> 7, n = idx & 127;
        ts[k][n] = src[(size_t)k * ldsrc + n];
    }
    __syncthreads();
    int n = t >> 1, half = t & 1;
    float f[16];
#pragma unroll
    for (int j = 0; j < 16; ++j) f[j] = ts[half * 16 + j][n];
    uint32_t hi[8], lo[8];
#pragma unroll
    for (int j = 0; j < 8; ++j)
        split_pack(f[j * 2], f[j * 2 + 1], hi[j], lo[j]);
    size_t o = dstE + (size_t)n * 40 + half * 16;
    uint4* ph = reinterpret_cast<uint4*>(dh + o);
    uint4* pl = reinterpret_cast<uint4*>(dl + o);
    const uint4* sh = reinterpret_cast<const uint4*>(hi);
    const uint4* sl = reinterpret_cast<const uint4*>(lo);
    ph[0] = sh[0]; ph[1] = sh[1];
    pl[0] = sl[0]; pl[1] = sl[1];
}

__global__ void init_out_kernel(const float* __restrict__ p_hat,
                                const float* __restrict__ b3,
                                float* __restrict__ out) {
    int i = blockIdx.x * blockDim.x + threadIdx.x;
    int b = i >> 8, c = i & 255;
    float s = 0.f;
#pragma unroll
    for (int k = 0; k < KEXP; ++k)
        s = fmaf(p_hat[(size_t)b * KEXP + k], b3[k * LAT + c], s);
    out[i] = s;
}

// =========================== main kernel (exact R12) ========================
#define FILL4(xh_, xl_, wh_, wl_) do { \
    int s_ = pg % 3; uint32_t par_ = (uint32_t)(((pg / 3) + 1) & 1); \
    uint32_t fb_ = mb0 + s_ * 16, eb_ = fb_ + 8; \
    mbar_wait(eb_, par_); \
    MBAR_EXPECT_TX(fb_, 4 * TILEB); \
    bulk_g2s(sb + STG(s_, 0), (xh_), TILEB, fb_); \
    bulk_g2s(sb + STG(s_, 1), (xl_), TILEB, fb_); \
    bulk_g2s(sb + STG(s_, 2), (wh_), TILEB, fb_); \
    bulk_g2s(sb + STG(s_, 3), (wl_), TILEB, fb_); \
    ++pg; } while (0)

#define FILL2(wh_, wl_) do { \
    int s_ = pg % 3; uint32_t par_ = (uint32_t)(((pg / 3) + 1) & 1); \
    uint32_t fb_ = mb0 + s_ * 16, eb_ = fb_ + 8; \
    mbar_wait(eb_, par_); \
    MBAR_EXPECT_TX(fb_, 2 * TILEB); \
    bulk_g2s(sb + STG(s_, 2), (wh_), TILEB, fb_); \
    bulk_g2s(sb + STG(s_, 3), (wl_), TILEB, fb_); \
    ++pg; } while (0)

__global__ __launch_bounds__(512, 1)
void phase_moe_mma(const float* __restrict__ tau,
                   const float* __restrict__ p_hat,
                   const float* __restrict__ W1,
                   const float* __restrict__ b1,
                   const float* __restrict__ b2,
                   float* __restrict__ out) {
    extern __shared__ __align__(128) char smem[];
    const uint32_t sb = smem_u32(smem);
    const int tid  = threadIdx.x;
    const int lane = tid & 31;
    const int w    = tid >> 5;
    const int wm   = w >> 2, wn = w & 3;
    const int lr   = lane >> 2, lc = lane & 3;
    const int b0   = blockIdx.x * 128;
    const int btile = blockIdx.x;

    const uint32_t aoff = (uint32_t)(((lane & 7) + ((lane >> 3) & 1) * 8) * ROWB
                                     + ((lane >> 4) & 1) * 16);
    const uint32_t boff = (uint32_t)(((lane & 7) + ((lane >> 4) & 1) * 8) * ROWB
                                     + ((lane >> 3) & 1) * 16);

    float* b1s  = reinterpret_cast<float*>(smem + AUX);          // 128
    float* b2s  = reinterpret_cast<float*>(smem + AUX + 512);    // 128
    float* w1l  = reinterpret_cast<float*>(smem + AUX + 1024);   // 128
    float* taus = reinterpret_cast<float*>(smem + AUX + 1536);   // 128
    const uint32_t mb0 = sb + AUX + 2048;                        // 3x(full,empty)

    if (tid == 0) {
#pragma unroll
        for (int s = 0; s < 3; ++s) {
            MBAR_INIT(mb0 + s * 16,     1);    // full: expect_tx arrival
            MBAR_INIT(mb0 + s * 16 + 8, 16);   // empty: one arrive per warp
        }
    }
    if (tid < 128) taus[tid] = tau[b0 + tid];
    __syncthreads();   // mbarrier init visible

    int pg = 0;   // producer fill counter (tid0)
    int cg = 0;   // consumer counter (all threads)
    float c[2][4][4];

    for (int e = 0; e < KEXP; ++e) {
        __syncthreads();   // bias smem reuse safe; h tiles free
        if (tid < 128) {
            b1s[tid] = b1[e * HID + tid];
            b2s[tid] = b2[e * HID + tid];
            w1l[tid] = W1[((size_t)e * 1281 + 1280) * HID + tid];
        }

        // ---------------- layer 1: K=1280, 40 chunks ------------------------
        const __nv_bfloat16* xh  = g_xhi  + (size_t)btile * 40 * TILEE;
        const __nv_bfloat16* xl  = g_xlo  + (size_t)btile * 40 * TILEE;
        const __nv_bfloat16* w1h = g_w1hi + (size_t)e * 40 * TILEE;
        const __nv_bfloat16* w1o = g_w1lo + (size_t)e * 40 * TILEE;
        ZERO_C();
        if (tid == 0) {
            FILL4(xh, xl, w1h, w1o);
            FILL4(xh + TILEE, xl + TILEE, w1h + TILEE, w1o + TILEE);
        }
        for (int ch = 0; ch < 40; ++ch) {
            if (tid == 0 && ch + 2 < 40) {
                size_t o = (size_t)(ch + 2) * TILEE;
                FILL4(xh + o, xl + o, w1h + o, w1o + o);
            }
            int s_ = cg % 3;
            consume_l1(c, sb, s_, mb0 + s_ * 16, (uint32_t)((cg / 3) & 1),
                       wm, wn, aoff, boff, lane);
            ++cg;
        }

        // producer: prefetch L2 chunks 0,1 (overlaps L1 epilogue)
        const __nv_bfloat16* w2h = g_w2hi + (size_t)e * 4 * TILEE;
        const __nv_bfloat16* w2l = g_w2lo + (size_t)e * 4 * TILEE;
        if (tid == 0) {
            FILL2(w2h, w2l);
            FILL2(w2h + TILEE, w2l + TILEE);
        }
        if (tid != 0) pg += 2;

        // L1 epilogue: +bias +tau*w1last, silu, split -> h tiles (chunk = wn)
#pragma unroll
        for (int mt = 0; mt < 2; ++mt)
#pragma unroll
            for (int nt = 0; nt < 4; ++nt)
#pragma unroll
                for (int pr = 0; pr < 2; ++pr) {
                    int m   = wm * 32 + mt * 16 + pr * 8 + lr;
                    int col = wn * 32 + nt * 8 + lc * 2;
                    float t  = taus[m];
                    float v0 = c[mt][nt][pr * 2]     + b1s[col]     + t * w1l[col];
                    float v1 = c[mt][nt][pr * 2 + 1] + b1s[col + 1] + t * w1l[col + 1];
                    float h0 = v0 / (1.f + __expf(-v0));
                    float h1 = v1 / (1.f + __expf(-v1));
                    uint32_t hip, lop;
                    split_pack(h0, h1, hip, lop);
                    uint32_t byte = (uint32_t)(m * ROWB + (nt * 8 + lc * 2) * 2);
                    *(uint32_t*)(smem + HOF(wn, 0) + byte) = hip;
                    *(uint32_t*)(smem + HOF(wn, 1) + byte) = lop;
                }
        __syncthreads();   // h visible to all warps

        // ---------------- layer 2: K=128, 4 chunks --------------------------
        ZERO_C();
        for (int ch = 0; ch < 4; ++ch) {
            if (tid == 0 && ch + 2 < 4) {
                size_t o = (size_t)(ch + 2) * TILEE;
                FILL2(w2h + o, w2l + o);
            }
            if (tid != 0 && ch + 2 < 4) ++pg;
            int s_ = cg % 3;
            consume_h(c, sb, HOF(ch, 0), HOF(ch, 1), s_, mb0 + s_ * 16,
                      (uint32_t)((cg / 3) & 1), wm, wn, aoff, boff, lane);
            ++cg;
        }
        // all warps must finish reading HOF before the L2 epilogue overwrites
        __syncthreads();

        // producer: prefetch L3 nh=0 chunks 0,1 (overlaps L2 epilogue)
        const __nv_bfloat16* w3h = g_w3hi + (size_t)e * 8 * TILEE;
        const __nv_bfloat16* w3l = g_w3lo + (size_t)e * 8 * TILEE;
        if (tid == 0) {
            FILL2(w3h, w3l);
            FILL2(w3h + TILEE, w3l + TILEE);
        }
        if (tid != 0) pg += 2;

        // L2 epilogue: +bias, silu, *p -> h tiles
#pragma unroll
        for (int mt = 0; mt < 2; ++mt)
#pragma unroll
            for (int nt = 0; nt < 4; ++nt)
#pragma unroll
                for (int pr = 0; pr < 2; ++pr) {
                    int m   = wm * 32 + mt * 16 + pr * 8 + lr;
                    int col = wn * 32 + nt * 8 + lc * 2;
                    float pe = p_hat[(size_t)(b0 + m) * KEXP + e];
                    float v0 = c[mt][nt][pr * 2]     + b2s[col];
                    float v1 = c[mt][nt][pr * 2 + 1] + b2s[col + 1];
                    float h0 = pe * (v0 / (1.f + __expf(-v0)));
                    float h1 = pe * (v1 / (1.f + __expf(-v1)));
                    uint32_t hip, lop;
                    split_pack(h0, h1, hip, lop);
                    uint32_t byte = (uint32_t)(m * ROWB + (nt * 8 + lc * 2) * 2);
                    *(uint32_t*)(smem + HOF(wn, 0) + byte) = hip;
                    *(uint32_t*)(smem + HOF(wn, 1) + byte) = lop;
                }
        __syncthreads();   // new h visible to all warps

        // ---------------- layer 3: two 128-col halves, K=128 ----------------
        for (int nh = 0; nh < 2; ++nh) {
            const __nv_bfloat16* bh = w3h + (size_t)nh * 4 * TILEE;
            const __nv_bfloat16* bl = w3l + (size_t)nh * 4 * TILEE;
            if (nh == 1) {
                if (tid == 0) {
                    FILL2(bh, bl);
                    FILL2(bh + TILEE, bl + TILEE);
                }
                if (tid != 0) pg += 2;
            }
            ZERO_C();
            for (int ch = 0; ch < 4; ++ch) {
                if (tid == 0 && ch + 2 < 4) {
                    size_t o = (size_t)(ch + 2) * TILEE;
                    FILL2(bh + o, bl + o);
                }
                if (tid != 0 && ch + 2 < 4) ++pg;
                int s_ = cg % 3;
                consume_h(c, sb, HOF(ch, 0), HOF(ch, 1), s_, mb0 + s_ * 16,
                          (uint32_t)((cg / 3) & 1), wm, wn, aoff, boff, lane);
                ++cg;
            }
            // epilogue: out += D3 (p folded into h2; base = sum_k p*b3 via init)
#pragma unroll
            for (int mt = 0; mt < 2; ++mt)
#pragma unroll
                for (int nt = 0; nt < 4; ++nt)
#pragma unroll
                    for (int pr = 0; pr < 2; ++pr) {
                        int m   = wm * 32 + mt * 16 + pr * 8 + lr;
                        int col = nh * 128 + wn * 32 + nt * 8 + lc * 2;
                        float* o = out + (size_t)(b0 + m) * LAT + col;
                        float2 v = *reinterpret_cast<float2*>(o);
                        v.x += c[mt][nt][pr * 2];
                        v.y += c[mt][nt][pr * 2 + 1];
                        *reinterpret_cast<float2*>(o) = v;
                    }
        }
    }  // experts
}

// ============================== launch ======================================
extern "C" void kernel_launch(void* const* d_in, const int* in_sizes, int n_in,
                              void* d_out, int out_size) {
    const float* cond = (const float*)d_in[0];
    const float* u    = (const float*)d_in[1];
    const float* tau  = (const float*)d_in[2];
    const float* p    = (const float*)d_in[3];
    const float* W1   = (const float*)d_in[4];
    const float* b1   = (const float*)d_in[5];
    const float* W2   = (const float*)d_in[6];
    const float* b2   = (const float*)d_in[7];
    const float* W3   = (const float*)d_in[8];
    const float* b3   = (const float*)d_in[9];
    float* out = (float*)d_out;

    static int configured = 0;
    if (!configured) {
        cudaFuncSetAttribute(phase_moe_mma,
                             cudaFuncAttributeMaxDynamicSharedMemorySize,
                             SMEM_TOTAL);
        configured = 1;
    }

    convert_x_kernel<<<256 * 40, 256>>>(u, cond);
    convert_w_kernel<<<416, 256>>>(W1, W2, W3);
    init_out_kernel<<<(B_TOK * LAT) / 256, 256>>>(p, b3, out);
    phase_moe_mma<<<B_TOK / 128, 512, SMEM_TOTAL>>>(tau, p, W1, b1, b2, out);
}